// round 13
// baseline (speedup 1.0000x reference)
#include <cuda_runtime.h>
#include <cuda_fp16.h>
#include <cstdint>

// ---------------- problem constants ----------------
#define BN 32
#define TN 2048
#define HN 1024
#define UN 1024
#define SZ (BN * TN)

// ---------------- device scratch (no cudaMalloc allowed) ----------------
__device__ float  g_qbias[BN * UN];          // q@Wq^T + W_b (fp32, exact)
__device__ float  g_scp[8 * SZ];             // per-N-eighth partial scores
__device__ __half g_vf16[BN * TN * HN];      // values in fp16 (128MB)
__device__ __half g_wv16[UN * HN];           // Wv = W_w[:, :H] in fp16 (2MB)

// ---------------- helpers ----------------
__device__ __forceinline__ uint32_t smem_u32(const void* p) {
    uint32_t a;
    asm("{ .reg .u64 t; cvta.to.shared.u64 t, %1; cvt.u32.u64 %0, t; }" : "=r"(a) : "l"(p));
    return a;
}
__device__ __forceinline__ void mma16(float* d, const uint32_t* a, uint32_t b0, uint32_t b1) {
    asm volatile(
        "mma.sync.aligned.m16n8k16.row.col.f32.f16.f16.f32 "
        "{%0,%1,%2,%3}, {%4,%5,%6,%7}, {%8,%9}, {%0,%1,%2,%3};"
        : "+f"(d[0]), "+f"(d[1]), "+f"(d[2]), "+f"(d[3])
        : "r"(a[0]), "r"(a[1]), "r"(a[2]), "r"(a[3]), "r"(b0), "r"(b1));
}
__device__ __forceinline__ void ldsm4(uint32_t* r, uint32_t addr) {
    asm volatile("ldmatrix.sync.aligned.m8n8.x4.shared.b16 {%0,%1,%2,%3}, [%4];"
        : "=r"(r[0]), "=r"(r[1]), "=r"(r[2]), "=r"(r[3]) : "r"(addr));
}
#define CP16(dst, src) \
    asm volatile("cp.async.cg.shared.global [%0], [%1], 16;" :: "r"(dst), "l"(src))
#define CP_COMMIT() asm volatile("cp.async.commit_group;" ::: "memory")

// ---------------- gemm smem layout ----------------
// Stage (32KB): A [128 rows x 128B] + B [128 rows x 128B], rows = one K64 slab.
// XOR swizzle within a row: 16B-chunk c stored at (c ^ (row&7)). 3 stages = 96KB.
#define STG_BYTES 32768u
#define OFF_QB_F 24576   // = 3*STG_BYTES/4
#define OFF_VW_F 24704
#define OFF_SC_F 24832
#define SMEM_BYTES 100352   // (24576+128+128+256)*4

// =================== conversion kernels ===================
__global__ void __launch_bounds__(256) cvt_values_kernel(const float* __restrict__ src) {
    int i = blockIdx.x * 256 + threadIdx.x;
    const int stride = gridDim.x * 256;
    const int n8 = BN * TN * HN / 8;
    for (; i < n8; i += stride) {
        float4 f0 = ((const float4*)src)[2 * i];
        float4 f1 = ((const float4*)src)[2 * i + 1];
        __half2 h0 = __floats2half2_rn(f0.x, f0.y);
        __half2 h1 = __floats2half2_rn(f0.z, f0.w);
        __half2 h2 = __floats2half2_rn(f1.x, f1.y);
        __half2 h3 = __floats2half2_rn(f1.z, f1.w);
        uint4 u;
        u.x = *reinterpret_cast<unsigned*>(&h0);
        u.y = *reinterpret_cast<unsigned*>(&h1);
        u.z = *reinterpret_cast<unsigned*>(&h2);
        u.w = *reinterpret_cast<unsigned*>(&h3);
        reinterpret_cast<uint4*>(g_vf16)[i] = u;
    }
}
__global__ void __launch_bounds__(256) cvt_wv_kernel(const float* __restrict__ W) {
    // Wv = W_w[:, :HN]; row stride 2*HN
    int i = blockIdx.x * 256 + threadIdx.x;            // one per 8 elems; 131072 total
    int u = i >> 7, c8 = i & 127;
    const float4* s = (const float4*)(W + (size_t)u * (2 * HN) + c8 * 8);
    float4 f0 = s[0], f1 = s[1];
    __half2 h0 = __floats2half2_rn(f0.x, f0.y);
    __half2 h1 = __floats2half2_rn(f0.z, f0.w);
    __half2 h2 = __floats2half2_rn(f1.x, f1.y);
    __half2 h3 = __floats2half2_rn(f1.z, f1.w);
    uint4 v;
    v.x = *reinterpret_cast<unsigned*>(&h0);
    v.y = *reinterpret_cast<unsigned*>(&h1);
    v.z = *reinterpret_cast<unsigned*>(&h2);
    v.w = *reinterpret_cast<unsigned*>(&h3);
    reinterpret_cast<uint4*>(g_wv16)[i] = v;
}

// =================== kernel 0: qbias[b][u] = q[b] . Wq[u] + W_b[u] (fp32) ===================
__global__ void __launch_bounds__(256) qbias_kernel(const float* __restrict__ q,
                                                    const float* __restrict__ W,
                                                    const float* __restrict__ Wb) {
    int tid = threadIdx.x, lane = tid & 31, w = tid >> 5;
    int u = blockIdx.x * 8 + w;
    const float* wrow = W + (size_t)u * (2 * HN) + HN;   // Wq = W_w[:, H:]
    float wreg[32];
#pragma unroll
    for (int i = 0; i < 32; i++) wreg[i] = wrow[lane + i * 32];
    float wb = Wb[u];
    for (int b = 0; b < BN; b++) {
        const float* qb = q + b * HN;
        float acc = 0.f;
#pragma unroll
        for (int i = 0; i < 32; i++) acc = fmaf(wreg[i], qb[lane + i * 32], acc);
#pragma unroll
        for (int o = 16; o; o >>= 1) acc += __shfl_xor_sync(0xFFFFFFFFu, acc, o);
        if (lane == 0) g_qbias[b * UN + u] = acc + wb;
    }
}

// =================== kernel 1: fused fp16 GEMM + tanh reduce ===================
// Work unit = (m-tile, n-eighth): M=128 x N=128 x K=1024, 16 slabs of K=64.
// grid = 4096, MT-MAJOR: q = bid & 7, mt = bid >> 3 — 8 consecutive CTAs share
// one A m-tile (A read from DRAM once, 8x L2 reuse); B (2MB) is L2-resident.
// 256 thr, 8 warps (4M x 2N), warp tile 32x64. 3-stage cp.async, wait_group 1.
// TWO CTAs co-resident per SM cover each other's barrier bubbles.
__global__ void __launch_bounds__(256, 2)
gemm_score_kernel(const float* __restrict__ Vw) {
    extern __shared__ float sm[];
    const uint32_t sbase = smem_u32(sm);
    const int tid = threadIdx.x;
    const int lane = tid & 31, wid = tid >> 5;
    const int wm = wid & 3, wn = wid >> 2;         // 4 (M) x 2 (N)
    const int q  = blockIdx.x & 7;                 // n-eighth 0..7
    const int mt = blockIdx.x >> 3;                // m-tile 0..511
    const size_t m0 = (size_t)mt * 128;
    const int b = mt >> 4;                         // 16 M-tiles per batch
    const int u0 = q * 128;

    sm[OFF_SC_F + tid] = 0.f;                      // 256 score partials (128 rows x 2 wn)
    if (tid < 128) {
        sm[OFF_QB_F + tid] = g_qbias[b * UN + u0 + tid];
        sm[OFF_VW_F + tid] = Vw[u0 + tid];
    }

    const int l7 = lane & 7;
    const int hiA = lane >> 4;                     // A k-chunk select (0/1)
    const int hiB = (lane >> 3) & 1;               // B k-chunk select (0/1)
    const uint32_t aRow = (uint32_t)(wm * 32 + (lane & 15)) * 128u;
    const uint32_t bRow = 16384u +
        (uint32_t)(wn * 64 + ((lane >> 4) & 1) * 8 + l7) * 128u;

    auto load_slab = [&](int g) {
        const int k0 = g * 64;
        const uint32_t st = sbase + (uint32_t)(g % 3) * STG_BYTES;
#pragma unroll
        for (int i = 0; i < 4; i++) {              // A: 128 rows x 8 16B-chunks
            int idx = tid + i * 256;
            int row = idx >> 3, gc = idx & 7;
            uint32_t dst = st + (uint32_t)row * 128u +
                           (uint32_t)((gc ^ (row & 7)) << 4);
            CP16(dst, g_vf16 + (m0 + row) * HN + k0 + gc * 8);
        }
#pragma unroll
        for (int i = 0; i < 4; i++) {              // B: 128 rows x 8 16B-chunks
            int idx = tid + i * 256;
            int row = idx >> 3, gc = idx & 7;
            uint32_t dst = st + 16384u + (uint32_t)row * 128u +
                           (uint32_t)((gc ^ (row & 7)) << 4);
            CP16(dst, g_wv16 + (size_t)(u0 + row) * HN + k0 + gc * 8);
        }
        CP_COMMIT();
    };

    float acc[2][8][4];
#pragma unroll
    for (int i = 0; i < 2; i++)
#pragma unroll
        for (int j = 0; j < 8; j++)
#pragma unroll
            for (int k = 0; k < 4; k++) acc[i][j][k] = 0.f;

    load_slab(0);
    load_slab(1);

    for (int g = 0; g < 16; g++) {
        asm volatile("cp.async.wait_group 1;" ::: "memory");
        __syncthreads();
        if (g + 2 < 16) load_slab(g + 2);
        else CP_COMMIT();                          // keep group accounting

        const uint32_t st = sbase + (uint32_t)(g % 3) * STG_BYTES;
        const uint32_t aB = st + aRow;
        const uint32_t bB = st + bRow;
#pragma unroll
        for (int kk = 0; kk < 4; kk++) {           // 4 x k16
            const int c0 = kk * 2;
            const uint32_t swA = (uint32_t)(((c0 + hiA) ^ l7) << 4);
            const uint32_t swB = (uint32_t)(((c0 + hiB) ^ l7) << 4);
            uint32_t af[2][4], bf[4][4];
#pragma unroll
            for (int ms = 0; ms < 2; ms++)
                ldsm4(af[ms], aB + (uint32_t)ms * 2048u + swA);
#pragma unroll
            for (int j = 0; j < 4; j++)
                ldsm4(bf[j], bB + (uint32_t)j * 2048u + swB);
#pragma unroll
            for (int ms = 0; ms < 2; ms++)
#pragma unroll
                for (int j = 0; j < 4; j++) {
                    mma16(acc[ms][2 * j],     af[ms], bf[j][0], bf[j][1]);
                    mma16(acc[ms][2 * j + 1], af[ms], bf[j][2], bf[j][3]);
                }
        }
    }

    // ---- epilogue: rsum[row] = sum_col tanh(acc + qbias) * Vw over this eighth ----
    float rsum[2][2];
#pragma unroll
    for (int ms = 0; ms < 2; ms++) { rsum[ms][0] = 0.f; rsum[ms][1] = 0.f; }
#pragma unroll
    for (int ms = 0; ms < 2; ms++)
#pragma unroll
        for (int ns = 0; ns < 8; ns++)
#pragma unroll
            for (int d = 0; d < 4; d++) {
                int col = wn * 64 + ns * 8 + (lane & 3) * 2 + (d & 1);
                float x = acc[ms][ns][d] + sm[OFF_QB_F + col];
                float e = __expf(x + x);
                float th = 1.f - 2.f / (e + 1.f);   // exact tanh, stable both tails
                rsum[ms][d >> 1] = fmaf(th, sm[OFF_VW_F + col], rsum[ms][d >> 1]);
            }
#pragma unroll
    for (int ms = 0; ms < 2; ms++)
#pragma unroll
        for (int hi = 0; hi < 2; hi++) {
            float v = rsum[ms][hi];
            v += __shfl_xor_sync(0xFFFFFFFFu, v, 1);
            v += __shfl_xor_sync(0xFFFFFFFFu, v, 2);
            if ((lane & 3) == 0) {
                int row = wm * 32 + ms * 16 + hi * 8 + (lane >> 2);
                sm[OFF_SC_F + row * 2 + wn] += v;   // unique (row, wn) writer
            }
        }
    __syncthreads();

    if (tid < 128)
        g_scp[q * SZ + m0 + tid] =
            sm[OFF_SC_F + tid * 2] + sm[OFF_SC_F + tid * 2 + 1];
}

// =================== kernel 2: fused softmax + context ===================
// grid (16, 32): 64-col chunk x batch; 256 thr. Every block recomputes its
// batch's softmax from g_scp (deterministic, identical across blocks);
// blockIdx.x==0 also writes the attention weights output.
__global__ void __launch_bounds__(256) ctx_softmax_kernel(float* __restrict__ out) {
    __shared__ float ws[TN];
    __shared__ float red[256];
    __shared__ float part[4][64];
    const int b = blockIdx.y;
    const int tid = threadIdx.x;

    // ---- softmax over T (sum 8 n-eighth partials) ----
    float loc[8];
    float mx = -1e30f;
#pragma unroll
    for (int i = 0; i < 8; i++) {
        int idx = b * TN + tid + i * 256;
        float s = 0.f;
#pragma unroll
        for (int qq = 0; qq < 8; qq++) s += g_scp[qq * SZ + idx];
        loc[i] = s;
        mx = fmaxf(mx, s);
    }
    red[tid] = mx; __syncthreads();
    for (int s = 128; s; s >>= 1) { if (tid < s) red[tid] = fmaxf(red[tid], red[tid + s]); __syncthreads(); }
    float m = red[0]; __syncthreads();
    float sum = 0.f;
#pragma unroll
    for (int i = 0; i < 8; i++) { loc[i] = __expf(loc[i] - m); sum += loc[i]; }
    red[tid] = sum; __syncthreads();
    for (int s = 128; s; s >>= 1) { if (tid < s) red[tid] += red[tid + s]; __syncthreads(); }
    float inv = 1.f / red[0];
#pragma unroll
    for (int i = 0; i < 8; i++) {
        float w = loc[i] * inv;
        ws[tid + i * 256] = w;
        if (blockIdx.x == 0)
            out[BN * HN + b * TN + tid + i * 256] = w;
    }
    __syncthreads();

    // ---- context: out[b][col] = sum_t ws[t] * values_f16[b][t][col] ----
    const int tc = tid & 63, tq = tid >> 6;
    const int col = blockIdx.x * 64 + tc;
    const __half* vp = g_vf16 + ((size_t)b * TN + tq * 512) * HN + col;
    float acc = 0.f;
#pragma unroll 16
    for (int t = 0; t < 512; t++)
        acc = fmaf(ws[tq * 512 + t], __half2float(vp[(size_t)t * HN]), acc);
    part[tq][tc] = acc;
    __syncthreads();
    if (tq == 0)
        out[b * HN + col] = part[0][tc] + part[1][tc] + part[2][tc] + part[3][tc];
}

// =================== launch ===================
extern "C" void kernel_launch(void* const* d_in, const int* in_sizes, int n_in,
                              void* d_out, int out_size) {
    const float* q      = (const float*)d_in[0];   // (1,32,1024)
    const float* values = (const float*)d_in[1];   // (32,2048,1024)
    const float* Ww     = (const float*)d_in[2];   // (1024,2048)
    const float* Wb     = (const float*)d_in[3];   // (1024,)
    const float* Vw     = (const float*)d_in[4];   // (1,1024)
    // d_in[5] = V_b : softmax-invariant, unused
    float* out = (float*)d_out;                    // [context 32*1024 | weights 32*2048]

    cvt_values_kernel<<<8192, 256>>>(values);
    cvt_wv_kernel<<<512, 256>>>(Ww);
    qbias_kernel<<<128, 256>>>(q, Ww, Wb);

    cudaFuncSetAttribute(gemm_score_kernel,
                         cudaFuncAttributeMaxDynamicSharedMemorySize, SMEM_BYTES);
    gemm_score_kernel<<<4096, 256, SMEM_BYTES>>>(Vw);

    ctx_softmax_kernel<<<dim3(16, 32), 256>>>(out);
}

// round 14
// speedup vs baseline: 1.0770x; 1.0770x over previous
#include <cuda_runtime.h>
#include <cuda_fp16.h>
#include <cstdint>

// ---------------- problem constants ----------------
#define BN 32
#define TN 2048
#define HN 1024
#define UN 1024
#define SZ (BN * TN)

// ---------------- device scratch (no cudaMalloc allowed) ----------------
__device__ float  g_qbias[BN * UN];          // q@Wq^T + W_b (fp32, exact)
__device__ float  g_scp[8 * SZ];             // per-N-eighth partial scores
__device__ __half g_vf16[BN * TN * HN];      // values in fp16 (128MB)
__device__ __half g_wv16[UN * HN];           // Wv = W_w[:, :H] in fp16 (2MB)

// ---------------- helpers ----------------
__device__ __forceinline__ uint32_t smem_u32(const void* p) {
    uint32_t a;
    asm("{ .reg .u64 t; cvta.to.shared.u64 t, %1; cvt.u32.u64 %0, t; }" : "=r"(a) : "l"(p));
    return a;
}
__device__ __forceinline__ void mma16(float* d, const uint32_t* a, uint32_t b0, uint32_t b1) {
    asm volatile(
        "mma.sync.aligned.m16n8k16.row.col.f32.f16.f16.f32 "
        "{%0,%1,%2,%3}, {%4,%5,%6,%7}, {%8,%9}, {%0,%1,%2,%3};"
        : "+f"(d[0]), "+f"(d[1]), "+f"(d[2]), "+f"(d[3])
        : "r"(a[0]), "r"(a[1]), "r"(a[2]), "r"(a[3]), "r"(b0), "r"(b1));
}
__device__ __forceinline__ void ldsm4(uint32_t* r, uint32_t addr) {
    asm volatile("ldmatrix.sync.aligned.m8n8.x4.shared.b16 {%0,%1,%2,%3}, [%4];"
        : "=r"(r[0]), "=r"(r[1]), "=r"(r[2]), "=r"(r[3]) : "r"(addr));
}
#define CP16(dst, src) \
    asm volatile("cp.async.cg.shared.global [%0], [%1], 16;" :: "r"(dst), "l"(src))
#define CP_COMMIT() asm volatile("cp.async.commit_group;" ::: "memory")

// ---------------- gemm smem layout ----------------
// Stage (32KB): A [128 rows x 128B] + B [128 rows x 128B], rows = one K64 slab.
// XOR swizzle within a row: 16B-chunk c stored at (c ^ (row&7)). 3 stages = 96KB.
#define STG_BYTES 32768u
#define OFF_QB_F 24576   // = 3*STG_BYTES/4
#define OFF_VW_F 24704
#define OFF_SC_F 24832
#define SMEM_BYTES 100352   // (24576+128+128+256)*4

// =================== prep kernel: qbias + cvt_wv + cvt_values fused ===================
// blocks [0,128): qbias; [128,640): cvt_wv; [640,8320): cvt_values (grid-stride).
// All three are independent; the two small jobs hide inside cvt_values' BW time.
__global__ void __launch_bounds__(256) prep_kernel(const float* __restrict__ q,
                                                   const float* __restrict__ W,
                                                   const float* __restrict__ Wb,
                                                   const float* __restrict__ values) {
    const int bid = blockIdx.x;
    const int tid = threadIdx.x;

    if (bid < 128) {
        // ---- qbias[b][u] = q[b] . Wq[u] + W_b[u] (fp32, exact) ----
        int lane = tid & 31, w = tid >> 5;
        int u = bid * 8 + w;
        const float* wrow = W + (size_t)u * (2 * HN) + HN;   // Wq = W_w[:, H:]
        float wreg[32];
#pragma unroll
        for (int i = 0; i < 32; i++) wreg[i] = wrow[lane + i * 32];
        float wb = Wb[u];
        for (int b = 0; b < BN; b++) {
            const float* qb = q + b * HN;
            float acc = 0.f;
#pragma unroll
            for (int i = 0; i < 32; i++) acc = fmaf(wreg[i], qb[lane + i * 32], acc);
#pragma unroll
            for (int o = 16; o; o >>= 1) acc += __shfl_xor_sync(0xFFFFFFFFu, acc, o);
            if (lane == 0) g_qbias[b * UN + u] = acc + wb;
        }
        return;
    }
    if (bid < 640) {
        // ---- cvt_wv: Wv = W_w[:, :HN] -> fp16; row stride 2*HN ----
        int i = (bid - 128) * 256 + tid;               // one per 8 elems; 131072 total
        int u = i >> 7, c8 = i & 127;
        const float4* s = (const float4*)(W + (size_t)u * (2 * HN) + c8 * 8);
        float4 f0 = s[0], f1 = s[1];
        __half2 h0 = __floats2half2_rn(f0.x, f0.y);
        __half2 h1 = __floats2half2_rn(f0.z, f0.w);
        __half2 h2 = __floats2half2_rn(f1.x, f1.y);
        __half2 h3 = __floats2half2_rn(f1.z, f1.w);
        uint4 v;
        v.x = *reinterpret_cast<unsigned*>(&h0);
        v.y = *reinterpret_cast<unsigned*>(&h1);
        v.z = *reinterpret_cast<unsigned*>(&h2);
        v.w = *reinterpret_cast<unsigned*>(&h3);
        reinterpret_cast<uint4*>(g_wv16)[i] = v;
        return;
    }
    // ---- cvt_values: values -> fp16, grid-stride over 7680 blocks ----
    {
        int i = (bid - 640) * 256 + tid;
        const int stride = (gridDim.x - 640) * 256;
        const int n8 = BN * TN * HN / 8;
        for (; i < n8; i += stride) {
            float4 f0 = ((const float4*)values)[2 * i];
            float4 f1 = ((const float4*)values)[2 * i + 1];
            __half2 h0 = __floats2half2_rn(f0.x, f0.y);
            __half2 h1 = __floats2half2_rn(f0.z, f0.w);
            __half2 h2 = __floats2half2_rn(f1.x, f1.y);
            __half2 h3 = __floats2half2_rn(f1.z, f1.w);
            uint4 u4;
            u4.x = *reinterpret_cast<unsigned*>(&h0);
            u4.y = *reinterpret_cast<unsigned*>(&h1);
            u4.z = *reinterpret_cast<unsigned*>(&h2);
            u4.w = *reinterpret_cast<unsigned*>(&h3);
            reinterpret_cast<uint4*>(g_vf16)[i] = u4;
        }
    }
}

// =================== kernel 1: fused fp16 GEMM + tanh reduce ===================
// Work unit = (m-tile, n-eighth): M=128 x N=128 x K=1024, 16 slabs of K=64.
// grid = 4096, MT-MAJOR: q = bid & 7, mt = bid >> 3 — 8 consecutive CTAs share
// one A m-tile (A read from DRAM once, 8x L2 reuse); B (2MB) is L2-resident.
// 256 thr, 8 warps (4M x 2N), warp tile 32x64. 3-stage cp.async, wait_group 1.
// TWO CTAs co-resident per SM cover each other's barrier bubbles.
__global__ void __launch_bounds__(256, 2)
gemm_score_kernel(const float* __restrict__ Vw) {
    extern __shared__ float sm[];
    const uint32_t sbase = smem_u32(sm);
    const int tid = threadIdx.x;
    const int lane = tid & 31, wid = tid >> 5;
    const int wm = wid & 3, wn = wid >> 2;         // 4 (M) x 2 (N)
    const int q  = blockIdx.x & 7;                 // n-eighth 0..7
    const int mt = blockIdx.x >> 3;                // m-tile 0..511
    const size_t m0 = (size_t)mt * 128;
    const int b = mt >> 4;                         // 16 M-tiles per batch
    const int u0 = q * 128;

    sm[OFF_SC_F + tid] = 0.f;                      // 256 score partials (128 rows x 2 wn)
    if (tid < 128) {
        sm[OFF_QB_F + tid] = g_qbias[b * UN + u0 + tid];
        sm[OFF_VW_F + tid] = Vw[u0 + tid];
    }

    const int l7 = lane & 7;
    const int hiA = lane >> 4;                     // A k-chunk select (0/1)
    const int hiB = (lane >> 3) & 1;               // B k-chunk select (0/1)
    const uint32_t aRow = (uint32_t)(wm * 32 + (lane & 15)) * 128u;
    const uint32_t bRow = 16384u +
        (uint32_t)(wn * 64 + ((lane >> 4) & 1) * 8 + l7) * 128u;

    auto load_slab = [&](int g) {
        const int k0 = g * 64;
        const uint32_t st = sbase + (uint32_t)(g % 3) * STG_BYTES;
#pragma unroll
        for (int i = 0; i < 4; i++) {              // A: 128 rows x 8 16B-chunks
            int idx = tid + i * 256;
            int row = idx >> 3, gc = idx & 7;
            uint32_t dst = st + (uint32_t)row * 128u +
                           (uint32_t)((gc ^ (row & 7)) << 4);
            CP16(dst, g_vf16 + (m0 + row) * HN + k0 + gc * 8);
        }
#pragma unroll
        for (int i = 0; i < 4; i++) {              // B: 128 rows x 8 16B-chunks
            int idx = tid + i * 256;
            int row = idx >> 3, gc = idx & 7;
            uint32_t dst = st + 16384u + (uint32_t)row * 128u +
                           (uint32_t)((gc ^ (row & 7)) << 4);
            CP16(dst, g_wv16 + (size_t)(u0 + row) * HN + k0 + gc * 8);
        }
        CP_COMMIT();
    };

    float acc[2][8][4];
#pragma unroll
    for (int i = 0; i < 2; i++)
#pragma unroll
        for (int j = 0; j < 8; j++)
#pragma unroll
            for (int k = 0; k < 4; k++) acc[i][j][k] = 0.f;

    load_slab(0);
    load_slab(1);

    for (int g = 0; g < 16; g++) {
        asm volatile("cp.async.wait_group 1;" ::: "memory");
        __syncthreads();
        if (g + 2 < 16) load_slab(g + 2);
        else CP_COMMIT();                          // keep group accounting

        const uint32_t st = sbase + (uint32_t)(g % 3) * STG_BYTES;
        const uint32_t aB = st + aRow;
        const uint32_t bB = st + bRow;
#pragma unroll
        for (int kk = 0; kk < 4; kk++) {           // 4 x k16
            const int c0 = kk * 2;
            const uint32_t swA = (uint32_t)(((c0 + hiA) ^ l7) << 4);
            const uint32_t swB = (uint32_t)(((c0 + hiB) ^ l7) << 4);
            uint32_t af[2][4], bf[4][4];
#pragma unroll
            for (int ms = 0; ms < 2; ms++)
                ldsm4(af[ms], aB + (uint32_t)ms * 2048u + swA);
#pragma unroll
            for (int j = 0; j < 4; j++)
                ldsm4(bf[j], bB + (uint32_t)j * 2048u + swB);
#pragma unroll
            for (int ms = 0; ms < 2; ms++)
#pragma unroll
                for (int j = 0; j < 4; j++) {
                    mma16(acc[ms][2 * j],     af[ms], bf[j][0], bf[j][1]);
                    mma16(acc[ms][2 * j + 1], af[ms], bf[j][2], bf[j][3]);
                }
        }
    }

    // ---- epilogue: rsum[row] = sum_col tanh(acc + qbias) * Vw over this eighth ----
    float rsum[2][2];
#pragma unroll
    for (int ms = 0; ms < 2; ms++) { rsum[ms][0] = 0.f; rsum[ms][1] = 0.f; }
#pragma unroll
    for (int ms = 0; ms < 2; ms++)
#pragma unroll
        for (int ns = 0; ns < 8; ns++)
#pragma unroll
            for (int d = 0; d < 4; d++) {
                int col = wn * 64 + ns * 8 + (lane & 3) * 2 + (d & 1);
                float x = acc[ms][ns][d] + sm[OFF_QB_F + col];
                float e = __expf(x + x);
                float th = 1.f - 2.f / (e + 1.f);   // exact tanh, stable both tails
                rsum[ms][d >> 1] = fmaf(th, sm[OFF_VW_F + col], rsum[ms][d >> 1]);
            }
#pragma unroll
    for (int ms = 0; ms < 2; ms++)
#pragma unroll
        for (int hi = 0; hi < 2; hi++) {
            float v = rsum[ms][hi];
            v += __shfl_xor_sync(0xFFFFFFFFu, v, 1);
            v += __shfl_xor_sync(0xFFFFFFFFu, v, 2);
            if ((lane & 3) == 0) {
                int row = wm * 32 + ms * 16 + hi * 8 + (lane >> 2);
                sm[OFF_SC_F + row * 2 + wn] += v;   // unique (row, wn) writer
            }
        }
    __syncthreads();

    if (tid < 128)
        g_scp[q * SZ + m0 + tid] =
            sm[OFF_SC_F + tid * 2] + sm[OFF_SC_F + tid * 2 + 1];
}

// =================== kernel 2: softmax over T per batch (sums 8 eighth partials) ===================
__global__ void __launch_bounds__(256) softmax_kernel(float* __restrict__ out) {
    __shared__ float red[256];
    int b = blockIdx.x, tid = threadIdx.x;
    float loc[8];
    float mx = -1e30f;
#pragma unroll
    for (int i = 0; i < 8; i++) {
        int idx = b * TN + tid + i * 256;
        float s = 0.f;
#pragma unroll
        for (int qq = 0; qq < 8; qq++) s += g_scp[qq * SZ + idx];
        loc[i] = s;
        mx = fmaxf(mx, s);
    }
    red[tid] = mx; __syncthreads();
    for (int s = 128; s; s >>= 1) { if (tid < s) red[tid] = fmaxf(red[tid], red[tid + s]); __syncthreads(); }
    float m = red[0]; __syncthreads();
    float sum = 0.f;
#pragma unroll
    for (int i = 0; i < 8; i++) { loc[i] = __expf(loc[i] - m); sum += loc[i]; }
    red[tid] = sum; __syncthreads();
    for (int s = 128; s; s >>= 1) { if (tid < s) red[tid] += red[tid + s]; __syncthreads(); }
    float inv = 1.f / red[0];
#pragma unroll
    for (int i = 0; i < 8; i++)
        out[BN * HN + b * TN + tid + i * 256] = loc[i] * inv;
}

// =================== kernel 3: context from fp16 values ===================
// grid (16, 32): 64-col chunk x batch; 256 thr = 64 cols x 4 T-slices.
__global__ void __launch_bounds__(256) context_kernel(float* __restrict__ out) {
    __shared__ float ws[TN];
    __shared__ float part[4][64];
    int b = blockIdx.y;
    int tid = threadIdx.x, tc = tid & 63, tq = tid >> 6;
    int col = blockIdx.x * 64 + tc;
    for (int i = tid; i < TN; i += 256) ws[i] = out[BN * HN + b * TN + i];
    __syncthreads();
    const __half* vp = g_vf16 + ((size_t)b * TN + tq * 512) * HN + col;
    float acc = 0.f;
#pragma unroll 16
    for (int t = 0; t < 512; t++)
        acc = fmaf(ws[tq * 512 + t], __half2float(vp[(size_t)t * HN]), acc);
    part[tq][tc] = acc;
    __syncthreads();
    if (tq == 0)
        out[b * HN + col] = part[0][tc] + part[1][tc] + part[2][tc] + part[3][tc];
}

// =================== launch ===================
extern "C" void kernel_launch(void* const* d_in, const int* in_sizes, int n_in,
                              void* d_out, int out_size) {
    const float* q      = (const float*)d_in[0];   // (1,32,1024)
    const float* values = (const float*)d_in[1];   // (32,2048,1024)
    const float* Ww     = (const float*)d_in[2];   // (1024,2048)
    const float* Wb     = (const float*)d_in[3];   // (1024,)
    const float* Vw     = (const float*)d_in[4];   // (1,1024)
    // d_in[5] = V_b : softmax-invariant, unused
    float* out = (float*)d_out;                    // [context 32*1024 | weights 32*2048]

    prep_kernel<<<8320, 256>>>(q, Ww, Wb, values);

    cudaFuncSetAttribute(gemm_score_kernel,
                         cudaFuncAttributeMaxDynamicSharedMemorySize, SMEM_BYTES);
    gemm_score_kernel<<<4096, 256, SMEM_BYTES>>>(Vw);

    softmax_kernel<<<32, 256>>>(out);

    context_kernel<<<dim3(16, 32), 256>>>(out);
}

// round 15
// speedup vs baseline: 1.1102x; 1.0308x over previous
#include <cuda_runtime.h>
#include <cuda_fp16.h>
#include <cstdint>

// ---------------- problem constants ----------------
#define BN 32
#define TN 2048
#define HN 1024
#define UN 1024
#define SZ (BN * TN)

// ---------------- device scratch (no cudaMalloc allowed) ----------------
__device__ float  g_qbias[BN * UN];          // q@Wq^T + W_b (fp32, exact)
__device__ float  g_scp[8 * SZ];             // per-N-eighth partial scores
__device__ __half g_vf16[BN * TN * HN];      // values in fp16 (128MB)
__device__ __half g_wv16[UN * HN];           // Wv = W_w[:, :H] in fp16 (2MB)

// ---------------- helpers ----------------
__device__ __forceinline__ uint32_t smem_u32(const void* p) {
    uint32_t a;
    asm("{ .reg .u64 t; cvta.to.shared.u64 t, %1; cvt.u32.u64 %0, t; }" : "=r"(a) : "l"(p));
    return a;
}
__device__ __forceinline__ void mma16(float* d, const uint32_t* a, uint32_t b0, uint32_t b1) {
    asm volatile(
        "mma.sync.aligned.m16n8k16.row.col.f32.f16.f16.f32 "
        "{%0,%1,%2,%3}, {%4,%5,%6,%7}, {%8,%9}, {%0,%1,%2,%3};"
        : "+f"(d[0]), "+f"(d[1]), "+f"(d[2]), "+f"(d[3])
        : "r"(a[0]), "r"(a[1]), "r"(a[2]), "r"(a[3]), "r"(b0), "r"(b1));
}
__device__ __forceinline__ void ldsm4(uint32_t* r, uint32_t addr) {
    asm volatile("ldmatrix.sync.aligned.m8n8.x4.shared.b16 {%0,%1,%2,%3}, [%4];"
        : "=r"(r[0]), "=r"(r[1]), "=r"(r[2]), "=r"(r[3]) : "r"(addr));
}
#define CP16(dst, src) \
    asm volatile("cp.async.cg.shared.global [%0], [%1], 16;" :: "r"(dst), "l"(src))
#define CP_COMMIT() asm volatile("cp.async.commit_group;" ::: "memory")

// ---------------- gemm smem layout ----------------
// Stage (32KB): A [128 rows x 128B] + B [128 rows x 128B], rows = one K64 slab.
// XOR swizzle within a row: 16B-chunk c stored at (c ^ (row&7)). 3 stages = 96KB.
#define STG_BYTES 32768u
#define OFF_QB_F 24576   // = 3*STG_BYTES/4
#define OFF_VW_F 24704
#define OFF_SC_F 24832
#define SMEM_BYTES 100352   // (24576+128+128+256)*4

// =================== prep kernel: qbias + cvt_wv + cvt_values fused ===================
// blocks [0,128): qbias; [128,640): cvt_wv; [640,8320): cvt_values (grid-stride).
__global__ void __launch_bounds__(256) prep_kernel(const float* __restrict__ q,
                                                   const float* __restrict__ W,
                                                   const float* __restrict__ Wb,
                                                   const float* __restrict__ values) {
    const int bid = blockIdx.x;
    const int tid = threadIdx.x;

    if (bid < 128) {
        // ---- qbias[b][u] = q[b] . Wq[u] + W_b[u] (fp32, exact) ----
        int lane = tid & 31, w = tid >> 5;
        int u = bid * 8 + w;
        const float* wrow = W + (size_t)u * (2 * HN) + HN;   // Wq = W_w[:, H:]
        float wreg[32];
#pragma unroll
        for (int i = 0; i < 32; i++) wreg[i] = wrow[lane + i * 32];
        float wb = Wb[u];
        for (int b = 0; b < BN; b++) {
            const float* qb = q + b * HN;
            float acc = 0.f;
#pragma unroll
            for (int i = 0; i < 32; i++) acc = fmaf(wreg[i], qb[lane + i * 32], acc);
#pragma unroll
            for (int o = 16; o; o >>= 1) acc += __shfl_xor_sync(0xFFFFFFFFu, acc, o);
            if (lane == 0) g_qbias[b * UN + u] = acc + wb;
        }
        return;
    }
    if (bid < 640) {
        // ---- cvt_wv: Wv = W_w[:, :HN] -> fp16; row stride 2*HN ----
        int i = (bid - 128) * 256 + tid;               // one per 8 elems; 131072 total
        int u = i >> 7, c8 = i & 127;
        const float4* s = (const float4*)(W + (size_t)u * (2 * HN) + c8 * 8);
        float4 f0 = s[0], f1 = s[1];
        __half2 h0 = __floats2half2_rn(f0.x, f0.y);
        __half2 h1 = __floats2half2_rn(f0.z, f0.w);
        __half2 h2 = __floats2half2_rn(f1.x, f1.y);
        __half2 h3 = __floats2half2_rn(f1.z, f1.w);
        uint4 v;
        v.x = *reinterpret_cast<unsigned*>(&h0);
        v.y = *reinterpret_cast<unsigned*>(&h1);
        v.z = *reinterpret_cast<unsigned*>(&h2);
        v.w = *reinterpret_cast<unsigned*>(&h3);
        reinterpret_cast<uint4*>(g_wv16)[i] = v;
        return;
    }
    // ---- cvt_values: values -> fp16, grid-stride over 7680 blocks ----
    {
        int i = (bid - 640) * 256 + tid;
        const int stride = (gridDim.x - 640) * 256;
        const int n8 = BN * TN * HN / 8;
        for (; i < n8; i += stride) {
            float4 f0 = ((const float4*)values)[2 * i];
            float4 f1 = ((const float4*)values)[2 * i + 1];
            __half2 h0 = __floats2half2_rn(f0.x, f0.y);
            __half2 h1 = __floats2half2_rn(f0.z, f0.w);
            __half2 h2 = __floats2half2_rn(f1.x, f1.y);
            __half2 h3 = __floats2half2_rn(f1.z, f1.w);
            uint4 u4;
            u4.x = *reinterpret_cast<unsigned*>(&h0);
            u4.y = *reinterpret_cast<unsigned*>(&h1);
            u4.z = *reinterpret_cast<unsigned*>(&h2);
            u4.w = *reinterpret_cast<unsigned*>(&h3);
            reinterpret_cast<uint4*>(g_vf16)[i] = u4;
        }
    }
}

// =================== kernel 1: fused fp16 GEMM + tanh reduce ===================
// Work unit = (m-tile, n-eighth): M=128 x N=128 x K=1024, 16 slabs of K=64.
// grid = 4096, MT-MAJOR: q = bid & 7, mt = bid >> 3 — 8 consecutive CTAs share
// one A m-tile (A read from DRAM once, 8x L2 reuse); B (2MB) is L2-resident.
// 256 thr, 8 warps (4M x 2N), warp tile 32x64. 3-stage cp.async, wait_group 1.
// TWO CTAs co-resident per SM cover each other's barrier bubbles.
__global__ void __launch_bounds__(256, 2)
gemm_score_kernel(const float* __restrict__ Vw) {
    extern __shared__ float sm[];
    const uint32_t sbase = smem_u32(sm);
    const int tid = threadIdx.x;
    const int lane = tid & 31, wid = tid >> 5;
    const int wm = wid & 3, wn = wid >> 2;         // 4 (M) x 2 (N)
    const int q  = blockIdx.x & 7;                 // n-eighth 0..7
    const int mt = blockIdx.x >> 3;                // m-tile 0..511
    const size_t m0 = (size_t)mt * 128;
    const int b = mt >> 4;                         // 16 M-tiles per batch
    const int u0 = q * 128;

    sm[OFF_SC_F + tid] = 0.f;                      // 256 score partials (128 rows x 2 wn)
    if (tid < 128) {
        sm[OFF_QB_F + tid] = g_qbias[b * UN + u0 + tid];
        sm[OFF_VW_F + tid] = Vw[u0 + tid];
    }

    const int l7 = lane & 7;
    const int hiA = lane >> 4;                     // A k-chunk select (0/1)
    const int hiB = (lane >> 3) & 1;               // B k-chunk select (0/1)
    const uint32_t aRow = (uint32_t)(wm * 32 + (lane & 15)) * 128u;
    const uint32_t bRow = 16384u +
        (uint32_t)(wn * 64 + ((lane >> 4) & 1) * 8 + l7) * 128u;

    auto load_slab = [&](int g) {
        const int k0 = g * 64;
        const uint32_t st = sbase + (uint32_t)(g % 3) * STG_BYTES;
#pragma unroll
        for (int i = 0; i < 4; i++) {              // A: 128 rows x 8 16B-chunks
            int idx = tid + i * 256;
            int row = idx >> 3, gc = idx & 7;
            uint32_t dst = st + (uint32_t)row * 128u +
                           (uint32_t)((gc ^ (row & 7)) << 4);
            CP16(dst, g_vf16 + (m0 + row) * HN + k0 + gc * 8);
        }
#pragma unroll
        for (int i = 0; i < 4; i++) {              // B: 128 rows x 8 16B-chunks
            int idx = tid + i * 256;
            int row = idx >> 3, gc = idx & 7;
            uint32_t dst = st + 16384u + (uint32_t)row * 128u +
                           (uint32_t)((gc ^ (row & 7)) << 4);
            CP16(dst, g_wv16 + (size_t)(u0 + row) * HN + k0 + gc * 8);
        }
        CP_COMMIT();
    };

    float acc[2][8][4];
#pragma unroll
    for (int i = 0; i < 2; i++)
#pragma unroll
        for (int j = 0; j < 8; j++)
#pragma unroll
            for (int k = 0; k < 4; k++) acc[i][j][k] = 0.f;

    load_slab(0);
    load_slab(1);

    for (int g = 0; g < 16; g++) {
        asm volatile("cp.async.wait_group 1;" ::: "memory");
        __syncthreads();
        if (g + 2 < 16) load_slab(g + 2);
        else CP_COMMIT();                          // keep group accounting

        const uint32_t st = sbase + (uint32_t)(g % 3) * STG_BYTES;
        const uint32_t aB = st + aRow;
        const uint32_t bB = st + bRow;
#pragma unroll
        for (int kk = 0; kk < 4; kk++) {           // 4 x k16
            const int c0 = kk * 2;
            const uint32_t swA = (uint32_t)(((c0 + hiA) ^ l7) << 4);
            const uint32_t swB = (uint32_t)(((c0 + hiB) ^ l7) << 4);
            uint32_t af[2][4], bf[4][4];
#pragma unroll
            for (int ms = 0; ms < 2; ms++)
                ldsm4(af[ms], aB + (uint32_t)ms * 2048u + swA);
#pragma unroll
            for (int j = 0; j < 4; j++)
                ldsm4(bf[j], bB + (uint32_t)j * 2048u + swB);
#pragma unroll
            for (int ms = 0; ms < 2; ms++)
#pragma unroll
                for (int j = 0; j < 4; j++) {
                    mma16(acc[ms][2 * j],     af[ms], bf[j][0], bf[j][1]);
                    mma16(acc[ms][2 * j + 1], af[ms], bf[j][2], bf[j][3]);
                }
        }
    }

    // ---- epilogue: rsum[row] = sum_col tanh(acc + qbias) * Vw over this eighth ----
    float rsum[2][2];
#pragma unroll
    for (int ms = 0; ms < 2; ms++) { rsum[ms][0] = 0.f; rsum[ms][1] = 0.f; }
#pragma unroll
    for (int ms = 0; ms < 2; ms++)
#pragma unroll
        for (int ns = 0; ns < 8; ns++)
#pragma unroll
            for (int d = 0; d < 4; d++) {
                int col = wn * 64 + ns * 8 + (lane & 3) * 2 + (d & 1);
                float x = acc[ms][ns][d] + sm[OFF_QB_F + col];
                float e = __expf(x + x);
                float th = 1.f - 2.f / (e + 1.f);   // exact tanh, stable both tails
                rsum[ms][d >> 1] = fmaf(th, sm[OFF_VW_F + col], rsum[ms][d >> 1]);
            }
#pragma unroll
    for (int ms = 0; ms < 2; ms++)
#pragma unroll
        for (int hi = 0; hi < 2; hi++) {
            float v = rsum[ms][hi];
            v += __shfl_xor_sync(0xFFFFFFFFu, v, 1);
            v += __shfl_xor_sync(0xFFFFFFFFu, v, 2);
            if ((lane & 3) == 0) {
                int row = wm * 32 + ms * 16 + hi * 8 + (lane >> 2);
                sm[OFF_SC_F + row * 2 + wn] += v;   // unique (row, wn) writer
            }
        }
    __syncthreads();

    if (tid < 128)
        g_scp[q * SZ + m0 + tid] =
            sm[OFF_SC_F + tid * 2] + sm[OFF_SC_F + tid * 2 + 1];
}

// =================== kernel 2: softmax over T per batch (sums 8 eighth partials) ===================
__global__ void __launch_bounds__(256) softmax_kernel(float* __restrict__ out) {
    __shared__ float red[256];
    int b = blockIdx.x, tid = threadIdx.x;
    float loc[8];
    float mx = -1e30f;
#pragma unroll
    for (int i = 0; i < 8; i++) {
        int idx = b * TN + tid + i * 256;
        float s = 0.f;
#pragma unroll
        for (int qq = 0; qq < 8; qq++) s += g_scp[qq * SZ + idx];
        loc[i] = s;
        mx = fmaxf(mx, s);
    }
    red[tid] = mx; __syncthreads();
    for (int s = 128; s; s >>= 1) { if (tid < s) red[tid] = fmaxf(red[tid], red[tid + s]); __syncthreads(); }
    float m = red[0]; __syncthreads();
    float sum = 0.f;
#pragma unroll
    for (int i = 0; i < 8; i++) { loc[i] = __expf(loc[i] - m); sum += loc[i]; }
    red[tid] = sum; __syncthreads();
    for (int s = 128; s; s >>= 1) { if (tid < s) red[tid] += red[tid + s]; __syncthreads(); }
    float inv = 1.f / red[0];
#pragma unroll
    for (int i = 0; i < 8; i++)
        out[BN * HN + b * TN + tid + i * 256] = loc[i] * inv;
}

// =================== kernel 3: context from fp16 values (half2, high-occupancy) ===================
// grid (32, 32): 32-col chunk x batch; 256 thr = 16 half2-lanes x 16 T-slices of 128.
__global__ void __launch_bounds__(256) context_kernel(float* __restrict__ out) {
    __shared__ float ws[TN];
    __shared__ float2 part[16][16];
    const int b = blockIdx.y;
    const int tid = threadIdx.x, tc = tid & 15, tq = tid >> 4;
    const int col2 = blockIdx.x * 16 + tc;         // half2 column index
    for (int i = tid; i < TN; i += 256) ws[i] = out[BN * HN + b * TN + i];
    __syncthreads();
    const __half2* vp =
        (const __half2*)(g_vf16 + ((size_t)b * TN + tq * 128) * HN) + col2;
    float2 acc = make_float2(0.f, 0.f);
#pragma unroll 16
    for (int t = 0; t < 128; t++) {
        float w = ws[tq * 128 + t];
        float2 v = __half22float2(vp[(size_t)t * (HN / 2)]);
        acc.x = fmaf(w, v.x, acc.x);
        acc.y = fmaf(w, v.y, acc.y);
    }
    part[tq][tc] = acc;
    __syncthreads();
    if (tq == 0) {
        float sx = 0.f, sy = 0.f;
#pragma unroll
        for (int i = 0; i < 16; i++) { sx += part[i][tc].x; sy += part[i][tc].y; }
        out[b * HN + col2 * 2]     = sx;
        out[b * HN + col2 * 2 + 1] = sy;
    }
}

// =================== launch ===================
extern "C" void kernel_launch(void* const* d_in, const int* in_sizes, int n_in,
                              void* d_out, int out_size) {
    const float* q      = (const float*)d_in[0];   // (1,32,1024)
    const float* values = (const float*)d_in[1];   // (32,2048,1024)
    const float* Ww     = (const float*)d_in[2];   // (1024,2048)
    const float* Wb     = (const float*)d_in[3];   // (1024,)
    const float* Vw     = (const float*)d_in[4];   // (1,1024)
    // d_in[5] = V_b : softmax-invariant, unused
    float* out = (float*)d_out;                    // [context 32*1024 | weights 32*2048]

    prep_kernel<<<8320, 256>>>(q, Ww, Wb, values);

    cudaFuncSetAttribute(gemm_score_kernel,
                         cudaFuncAttributeMaxDynamicSharedMemorySize, SMEM_BYTES);
    gemm_score_kernel<<<4096, 256, SMEM_BYTES>>>(Vw);

    softmax_kernel<<<32, 256>>>(out);

    context_kernel<<<dim3(32, 32), 256>>>(out);
}